// round 2
// baseline (speedup 1.0000x reference)
#include <cuda_runtime.h>
#include <cstdint>

#define IMG_H 1024
#define IMG_W 1024
#define NBATCH 16
#define PLANE_ELEMS (IMG_H * IMG_W)       // 1<<20
#define WORDS_PER_ROW 32                  // 1024 bits
#define PLANE_WORDS (IMG_H * WORDS_PER_ROW)
#define NITERS 5

// ---- device-global scratch (no-alloc rule) --------------------------------
__device__ float    g_buf0[(size_t)NBATCH * PLANE_ELEMS];   // pred field ping
__device__ float    g_buf1[(size_t)NBATCH * PLANE_ELEMS];   // pred field pong
__device__ unsigned g_tgtbits[(size_t)NBATCH * PLANE_WORDS]; // original target bits
__device__ unsigned g_gbits0[(size_t)NBATCH * PLANE_WORDS];  // gt field ping
__device__ unsigned g_gbits1[(size_t)NBATCH * PLANE_WORDS];  // gt field pong
__device__ float    g_partials[NBATCH * 64 * 2];             // (tp, ts) per chunk

__device__ __forceinline__ float sigmoidf_(float x) {
    return 1.0f / (1.0f + __expf(-x));
}
#define NEG_INF __int_as_float(0xff800000)

// ---------------------------------------------------------------------------
// init: pred planes = sigmoid(logits); pack target ints into bits (ballot).
// Two block ranges in one launch so both memory streams overlap.
// ---------------------------------------------------------------------------
__global__ void __launch_bounds__(256) init_kernel(
    const float4* __restrict__ lg4, const int* __restrict__ tgt)
{
    if (blockIdx.x < 2048) {
        const int total4 = (NBATCH * PLANE_ELEMS) / 4;   // 4M float4
        float4* p4 = reinterpret_cast<float4*>(g_buf0);
        int stride = 2048 * 256;
        for (int i = blockIdx.x * 256 + threadIdx.x; i < total4; i += stride) {
            float4 l = lg4[i];
            p4[i] = make_float4(sigmoidf_(l.x), sigmoidf_(l.y),
                                sigmoidf_(l.z), sigmoidf_(l.w));
        }
    } else {
        const int lane = threadIdx.x & 31;
        const int gw0  = (blockIdx.x - 2048) * 8 + (threadIdx.x >> 5);
        const int nw   = 512 * 8;
        const int totw = NBATCH * PLANE_WORDS;           // 512K words
        for (int w = gw0; w < totw; w += nw) {
            int v = tgt[(size_t)w * 32 + lane];
            unsigned m = __ballot_sync(0xffffffffu, v != 0);
            if (lane == 0) { g_tgtbits[w] = m; g_gbits0[w] = m; }
        }
    }
}

// ---------------------------------------------------------------------------
// fp32 soft-skeleton iteration (pred field), fully fused:
//   eroded = minpool3(x); opened = maxpool3(eroded);
//   x' = clip(x - (opened - eroded), 0, 1)
// Vertical taps: register rolling window. Horizontal taps: shfl.
// Erosion uses clamp-to-edge loads (== +inf SAME pad for min).
// Dilation masks out-of-image contributions to -inf explicitly.
// ---------------------------------------------------------------------------
__device__ __forceinline__ void step3(float xa, float xb, float xc, bool validc,
                                      float& e_out, float& h_out)
{
    float cm  = fminf(fminf(xa, xb), xc);                 // vertical min
    float cmL = __shfl_up_sync(0xffffffffu, cm, 1);
    float cmR = __shfl_down_sync(0xffffffffu, cm, 1);
    float e   = fminf(fminf(cmL, cmR), cm);               // eroded (this col)
    float em  = validc ? e : NEG_INF;                     // -inf pad for dilate
    float eL  = __shfl_up_sync(0xffffffffu, em, 1);
    float eR  = __shfl_down_sync(0xffffffffu, em, 1);
    h_out = fmaxf(fmaxf(eL, eR), em);                     // horiz max of eroded
    e_out = e;
}

__global__ void __launch_bounds__(256) iter_kernel(int srcsel)
{
    const int lane  = threadIdx.x & 31;
    const int warp  = threadIdx.x >> 5;
    const int plane = blockIdx.z;
    const float* __restrict__ src =
        (srcsel ? g_buf1 : g_buf0) + (size_t)plane * PLANE_ELEMS;
    float* __restrict__ dst =
        (srcsel ? g_buf0 : g_buf1) + (size_t)plane * PLANE_ELEMS;

    // 28 output cols per warp strip; lanes carry cols [base-2, base+29]
    const int colbase = blockIdx.x * 28 + lane - 2;
    const int col     = min(max(colbase, 0), IMG_W - 1);   // clamp (erosion ok)
    const bool validc = (colbase >= 0) && (colbase < IMG_W);
    const bool do_out = (lane >= 2) && (lane <= 29) && (colbase < IMG_W);

    const int r0 = (blockIdx.y * 8 + warp) * 64;           // 64 rows per warp

#define LDROW(r) src[(size_t)min(max((r), 0), IMG_H - 1) * IMG_W + col]

    float xa = LDROW(r0 - 2), xb = LDROW(r0 - 1), xc = LDROW(r0);
    float eT, hA, eB, hB;
    step3(xa, xb, xc, validc, eT, hA);     // row r0-1
    if (r0 == 0) hA = NEG_INF;             // row -1 doesn't exist for dilate
    xa = xb; xb = xc; xc = LDROW(r0 + 1);
    step3(xa, xb, xc, validc, eB, hB);     // row r0
    float x_r = xb;

#pragma unroll 4
    for (int r = r0; r < r0 + 64; ++r) {
        xa = xb; xb = xc; xc = LDROW(r + 2);
        float eC, hC;
        step3(xa, xb, xc, validc, eC, hC); // row r+1
        if (r + 1 >= IMG_H) hC = NEG_INF;  // row 1024 doesn't exist for dilate
        float opened = fmaxf(fmaxf(hA, hB), hC);
        float v = x_r - (opened - eB);
        v = fminf(fmaxf(v, 0.0f), 1.0f);
        if (do_out) dst[(size_t)r * IMG_W + colbase] = v;
        hA = hB; hB = hC; eB = eC; x_r = xb;
    }
#undef LDROW
}

// ---------------------------------------------------------------------------
// Bit-packed soft-skeleton iteration (gt field is binary and stays binary):
//   E = AND of 3x3 (pad 1), O = OR of 3x3 over E (pad 0), x' = x & ~(O & ~E)
// One warp spans a full row (32 words); neighbor words via shfl.
// ---------------------------------------------------------------------------
__device__ __forceinline__ unsigned hAND(unsigned c3, int lane)
{
    unsigned L = __shfl_up_sync(0xffffffffu, c3, 1);
    unsigned R = __shfl_down_sync(0xffffffffu, c3, 1);
    if (lane == 0)  L = 0xffffffffu;   // erosion pad = 1
    if (lane == 31) R = 0xffffffffu;
    return c3 & ((c3 << 1) | (L >> 31)) & ((c3 >> 1) | (R << 31));
}
__device__ __forceinline__ unsigned hOR(unsigned e, int lane)
{
    unsigned L = __shfl_up_sync(0xffffffffu, e, 1);
    unsigned R = __shfl_down_sync(0xffffffffu, e, 1);
    if (lane == 0)  L = 0u;            // dilation pad = 0
    if (lane == 31) R = 0u;
    return e | (e << 1) | (L >> 31) | (e >> 1) | (R << 31);
}

__global__ void __launch_bounds__(256) iter_bits_kernel(int srcsel)
{
    const int lane  = threadIdx.x & 31;    // word column 0..31
    const int warp  = threadIdx.x >> 5;
    const int plane = blockIdx.y;
    const unsigned* __restrict__ src =
        (srcsel ? g_gbits1 : g_gbits0) + (size_t)plane * PLANE_WORDS;
    unsigned* __restrict__ dst =
        (srcsel ? g_gbits0 : g_gbits1) + (size_t)plane * PLANE_WORDS;

    const int r0 = (blockIdx.x * 8 + warp) * 32;   // 32 rows per warp

#define LDW(r) (((r) < 0 || (r) >= IMG_H) ? 0xffffffffu : src[(r) * WORDS_PER_ROW + lane])

    unsigned xa = LDW(r0 - 2), xb = LDW(r0 - 1), xc = LDW(r0);
    unsigned c3 = xa & xb & xc;
    unsigned eT = hAND(c3, lane);
    unsigned hA = hOR(eT, lane);
    if (r0 == 0) hA = 0u;
    xa = xb; xb = xc; xc = LDW(r0 + 1);
    c3 = xa & xb & xc;
    unsigned eB = hAND(c3, lane);
    unsigned hB = hOR(eB, lane);
    unsigned xrow = xb;

#pragma unroll 4
    for (int r = r0; r < r0 + 32; ++r) {
        xa = xb; xb = xc; xc = LDW(r + 2);
        c3 = xa & xb & xc;
        unsigned eC = hAND(c3, lane);
        unsigned hC = hOR(eC, lane);
        if (r + 1 >= IMG_H) hC = 0u;
        unsigned O = hA | hB | hC;
        dst[r * WORDS_PER_ROW + lane] = xrow & ~(O & ~eB);
        hA = hB; hB = hC; eB = eC; xrow = xb;
    }
#undef LDW
}

// ---------------------------------------------------------------------------
// Partial sums per (batch, chunk):
//   tp = sum(skel_pred * tgt_bit),  ts = sum(skel_gt_bit * sigmoid(logit))
// Final fields: pred in g_buf1, gt bits in g_gbits1 (after 5 ping-pongs).
// ---------------------------------------------------------------------------
__global__ void __launch_bounds__(256) reduce_kernel(
    const float4* __restrict__ lg4)
{
    const int b = blockIdx.y, chunk = blockIdx.x, t = threadIdx.x;
    const size_t ebase = (size_t)b * PLANE_ELEMS + (size_t)chunk * 16384;

    const float4*   sp4 = reinterpret_cast<const float4*>(g_buf1) + ebase / 4;
    const float4*   l4  = lg4 + ebase / 4;
    const unsigned* tw  = g_tgtbits + ebase / 32;
    const unsigned* gw  = g_gbits1  + ebase / 32;

    float tp = 0.0f, ts = 0.0f;
    for (int i = t; i < 4096; i += 256) {
        float4 sp = sp4[i];
        unsigned w1 = tw[i >> 3];
        int sh = (i & 7) * 4;
        if ((w1 >> (sh + 0)) & 1) tp += sp.x;
        if ((w1 >> (sh + 1)) & 1) tp += sp.y;
        if ((w1 >> (sh + 2)) & 1) tp += sp.z;
        if ((w1 >> (sh + 3)) & 1) tp += sp.w;
        float4 l = l4[i];
        unsigned w2 = gw[i >> 3];
        if ((w2 >> (sh + 0)) & 1) ts += sigmoidf_(l.x);
        if ((w2 >> (sh + 1)) & 1) ts += sigmoidf_(l.y);
        if ((w2 >> (sh + 2)) & 1) ts += sigmoidf_(l.z);
        if ((w2 >> (sh + 3)) & 1) ts += sigmoidf_(l.w);
    }

    __shared__ float s1[256], s2[256];
    s1[t] = tp; s2[t] = ts;
    __syncthreads();
    for (int o = 128; o > 0; o >>= 1) {
        if (t < o) { s1[t] += s1[t + o]; s2[t] += s2[t + o]; }
        __syncthreads();
    }
    if (t == 0) {
        g_partials[(b * 64 + chunk) * 2 + 0] = s1[0];
        g_partials[(b * 64 + chunk) * 2 + 1] = s2[0];
    }
}

__global__ void final_kernel(float* __restrict__ out)
{
    __shared__ float terms[NBATCH];
    const int t = threadIdx.x;
    if (t < NBATCH) {
        float tp = 0.0f, ts = 0.0f;
        for (int c = 0; c < 64; ++c) {
            tp += g_partials[(t * 64 + c) * 2 + 0];
            ts += g_partials[(t * 64 + c) * 2 + 1];
        }
        float denom = tp + ts;
        float cl = (denom > 0.0f)
                 ? (2.0f * tp * ts + 1e-6f) / (denom + 1e-6f)
                 : 1.0f;
        cl = fminf(fmaxf(cl, 0.0f), 1.0f);
        terms[t] = 1.0f - cl;
    }
    __syncthreads();
    if (t == 0) {
        float s = 0.0f;
        for (int i = 0; i < NBATCH; ++i) s += terms[i];
        out[0] = s / (float)NBATCH;
    }
}

// ---------------------------------------------------------------------------
extern "C" void kernel_launch(void* const* d_in, const int* in_sizes, int n_in,
                              void* d_out, int out_size)
{
    const float4* lg4 = (const float4*)d_in[0];   // logits  fp32 [16,1,1024,1024]
    const int*    tgt = (const int*)d_in[1];      // target  int32 same shape

    init_kernel<<<2048 + 512, 256>>>(lg4, tgt);

    dim3 ig(37, 2, NBATCH);   // 37 col-strips x (2*8 warps * 64 rows) x 16 planes
    dim3 bg(4, NBATCH);       // 4 CTAs x 8 warps x 32 rows x 16 planes
    for (int k = 0; k < NITERS; ++k) {
        iter_kernel<<<ig, 256>>>(k & 1);
        iter_bits_kernel<<<bg, 256>>>(k & 1);
    }

    dim3 rg(64, NBATCH);
    reduce_kernel<<<rg, 256>>>(lg4);
    final_kernel<<<1, 32>>>((float*)d_out);
}

// round 4
// speedup vs baseline: 1.3768x; 1.3768x over previous
#include <cuda_runtime.h>
#include <cstdint>

#define IMG_H 1024
#define IMG_W 1024
#define NBATCH 16
#define PLANE_ELEMS (IMG_H * IMG_W)
#define WORDS_PER_ROW 32
#define PLANE_WORDS (IMG_H * WORDS_PER_ROW)
#define NITERS 5

#define POS_INF __int_as_float(0x7f800000)
#define NEG_INF __int_as_float(0xff800000)

// ---- device-global scratch (no-alloc rule) --------------------------------
__device__ float    g_buf0[(size_t)NBATCH * PLANE_ELEMS];
__device__ float    g_buf1[(size_t)NBATCH * PLANE_ELEMS];
__device__ unsigned g_tgtbits[(size_t)NBATCH * PLANE_WORDS];
__device__ unsigned g_gbits0[(size_t)NBATCH * PLANE_WORDS];
__device__ unsigned g_gbits1[(size_t)NBATCH * PLANE_WORDS];
__device__ float    g_tp_part[NBATCH * 32];
__device__ float    g_ts_part[NBATCH * 32];

__device__ __forceinline__ float sig1(float x) {
    return __fdividef(1.0f, 1.0f + __expf(-x));
}
__device__ __forceinline__ float min3f(float a, float b, float c) {
    return fminf(fminf(a, b), c);
}
__device__ __forceinline__ float max3f(float a, float b, float c) {
    return fmaxf(fmaxf(a, b), c);
}

// ---------------------------------------------------------------------------
// pack target ints into bit planes (1 bit/pixel)
// ---------------------------------------------------------------------------
__global__ void __launch_bounds__(256) pack_bits(const int4* __restrict__ tgt4)
{
    const int lane = threadIdx.x & 31;
    const int gw   = blockIdx.x * 8 + (threadIdx.x >> 5);
    const int nw   = gridDim.x * 8;
    const int tot4 = NBATCH * PLANE_WORDS / 4;   // warp covers 4 words/iter
    for (int q = gw; q < tot4; q += nw) {
        int4 v = tgt4[(size_t)q * 32 + lane];
        unsigned nib = (v.x != 0 ? 1u : 0u) | (v.y != 0 ? 2u : 0u)
                     | (v.z != 0 ? 4u : 0u) | (v.w != 0 ? 8u : 0u);
        unsigned part = nib << (4 * (lane & 7));
        unsigned grpmask = 0xFFu << (8 * (lane >> 3));
        unsigned word = __reduce_or_sync(grpmask, part);
        if ((lane & 7) == 0) {
            int w = q * 4 + (lane >> 3);
            g_tgtbits[w] = word;
            g_gbits0[w]  = word;
        }
    }
}

// ---------------------------------------------------------------------------
// Bit-packed soft-skeleton iteration for the binary gt field:
//   E = AND3x3 (pad 1), O = OR3x3 of E (pad 0), x' = x & ~(O & ~E)
// ---------------------------------------------------------------------------
__device__ __forceinline__ unsigned hAND(unsigned c3, int lane)
{
    unsigned L = __shfl_up_sync(0xffffffffu, c3, 1);
    unsigned R = __shfl_down_sync(0xffffffffu, c3, 1);
    if (lane == 0)  L = 0xffffffffu;
    if (lane == 31) R = 0xffffffffu;
    return c3 & ((c3 << 1) | (L >> 31)) & ((c3 >> 1) | (R << 31));
}
__device__ __forceinline__ unsigned hOR(unsigned e, int lane)
{
    unsigned L = __shfl_up_sync(0xffffffffu, e, 1);
    unsigned R = __shfl_down_sync(0xffffffffu, e, 1);
    if (lane == 0)  L = 0u;
    if (lane == 31) R = 0u;
    return e | (e << 1) | (L >> 31) | (e >> 1) | (R << 31);
}

__global__ void __launch_bounds__(256) iter_bits_kernel(int srcsel)
{
    const int lane  = threadIdx.x & 31;
    const int warp  = threadIdx.x >> 5;
    const int plane = blockIdx.y;
    const unsigned* __restrict__ src =
        (srcsel ? g_gbits1 : g_gbits0) + (size_t)plane * PLANE_WORDS;
    unsigned* __restrict__ dst =
        (srcsel ? g_gbits0 : g_gbits1) + (size_t)plane * PLANE_WORDS;

    const int r0 = (blockIdx.x * 8 + warp) * 32;

#define LDW(r) (((r) < 0 || (r) >= IMG_H) ? 0xffffffffu : src[(r) * WORDS_PER_ROW + lane])

    unsigned xa = LDW(r0 - 2), xb = LDW(r0 - 1), xc = LDW(r0);
    unsigned c3 = xa & xb & xc;
    unsigned hA = hOR(hAND(c3, lane), lane);
    if (r0 == 0) hA = 0u;
    xa = xb; xb = xc; xc = LDW(r0 + 1);
    c3 = xa & xb & xc;
    unsigned eB = hAND(c3, lane);
    unsigned hB = hOR(eB, lane);
    unsigned xrow = xb;

#pragma unroll 4
    for (int r = r0; r < r0 + 32; ++r) {
        xa = xb; xb = xc; xc = LDW(r + 2);
        c3 = xa & xb & xc;
        unsigned eC = hAND(c3, lane);
        unsigned hC = hOR(eC, lane);
        if (r + 1 >= IMG_H) hC = 0u;
        unsigned O = hA | hB | hC;
        dst[r * WORDS_PER_ROW + lane] = xrow & ~(O & ~eB);
        hA = hB; hB = hC; eB = eC; xrow = xb;
    }
#undef LDW
}

// ---------------------------------------------------------------------------
// Vectorized fp soft-skeleton iteration. MODE: 0=first (sigmoid in, ts out),
// 1=mid, 2=last (tp out, no field write).
// Each lane: 4 consecutive cols (float4); warp = 128-col strip.
// Horizontal taps via 4 shfl per row; strip halo via float2 on lanes 0/31.
// ---------------------------------------------------------------------------
template<int MODE>
__global__ void __launch_bounds__(256) iter_fp(const float* __restrict__ ext,
                                               int sel)
{
    const int lane  = threadIdx.x & 31;
    const int warp  = threadIdx.x >> 5;
    const int s     = blockIdx.x;       // strip 0..7
    const int plane = blockIdx.z;
    const bool isL = (lane == 0), isR = (lane == 31);

    const float* __restrict__ src = (MODE == 0)
        ? ext + (size_t)plane * PLANE_ELEMS
        : (sel ? g_buf1 : g_buf0) + (size_t)plane * PLANE_ELEMS;
    float* __restrict__ dst =
        (sel ? g_buf0 : g_buf1) + (size_t)plane * PLANE_ELEMS;

    const int colbase = s * 128 + lane * 4;
    const int r0 = (blockIdx.y * 8 + warp) * 32;

#define LOADROW(r, X, W) do {                                                 \
    const float* _p = src + (size_t)min(max((r), 0), IMG_H - 1) * IMG_W;      \
    X = *(const float4*)(_p + colbase);                                       \
    W = make_float2(POS_INF, POS_INF);                                        \
    if (isL) { if (s > 0) W = *(const float2*)(_p + s * 128 - 2); }           \
    else if (isR) { if (s < 7) W = *(const float2*)(_p + s * 128 + 128); }    \
    if (MODE == 0) {                                                          \
        X.x = sig1(X.x); X.y = sig1(X.y); X.z = sig1(X.z); X.w = sig1(X.w);   \
        W.x = sig1(W.x); W.y = sig1(W.y);                                     \
    }                                                                         \
} while (0)

#define STEP(A, B, C, WA, WB, WC, E, H) do {                                  \
    float m0 = min3f(A.x, B.x, C.x);                                          \
    float m1 = min3f(A.y, B.y, C.y);                                          \
    float m2 = min3f(A.z, B.z, C.z);                                          \
    float m3 = min3f(A.w, B.w, C.w);                                          \
    float mwx = min3f(WA.x, WB.x, WC.x);                                      \
    float mwy = min3f(WA.y, WB.y, WC.y);                                      \
    float mL = __shfl_up_sync(0xffffffffu, m3, 1);                            \
    float mR = __shfl_down_sync(0xffffffffu, m0, 1);                          \
    if (isL) mL = (s > 0) ? mwy : POS_INF;                                    \
    if (isR) mR = (s < 7) ? mwx : POS_INF;                                    \
    float e0 = min3f(mL, m0, m1);                                             \
    float e1 = min3f(m0, m1, m2);                                             \
    float e2 = min3f(m1, m2, m3);                                             \
    float e3 = min3f(m2, m3, mR);                                             \
    float eL = __shfl_up_sync(0xffffffffu, e3, 1);                            \
    float eR = __shfl_down_sync(0xffffffffu, e0, 1);                          \
    if (isL) eL = (s > 0) ? min3f(mwx, mwy, m0) : NEG_INF;                    \
    if (isR) eR = (s < 7) ? min3f(m3, mwx, mwy) : NEG_INF;                    \
    E = make_float4(e0, e1, e2, e3);                                          \
    H = make_float4(max3f(eL, e0, e1), max3f(e0, e1, e2),                     \
                    max3f(e1, e2, e3), max3f(e2, e3, eR));                    \
} while (0)

    float4 xa, xb, xc; float2 wa, wb, wc;
    LOADROW(r0 - 2, xa, wa);
    LOADROW(r0 - 1, xb, wb);
    LOADROW(r0,     xc, wc);
    float4 eT, hA;
    STEP(xa, xb, xc, wa, wb, wc, eT, hA);               // row r0-1
    if (r0 == 0) hA = make_float4(NEG_INF, NEG_INF, NEG_INF, NEG_INF);
    xa = xb; wa = wb; xb = xc; wb = wc;
    LOADROW(r0 + 1, xc, wc);
    float4 eB, hB;
    STEP(xa, xb, xc, wa, wb, wc, eB, hB);               // row r0
    float4 xr = xb;
    float acc = 0.0f;

#pragma unroll 4
    for (int r = r0; r < r0 + 32; ++r) {
        xa = xb; wa = wb; xb = xc; wb = wc;
        LOADROW(r + 2, xc, wc);
        float4 eC, hC;
        STEP(xa, xb, xc, wa, wb, wc, eC, hC);           // row r+1
        if (r + 1 >= IMG_H)
            hC = make_float4(NEG_INF, NEG_INF, NEG_INF, NEG_INF);

        float4 o;
        o.x = fminf(fmaxf(xr.x - (max3f(hA.x, hB.x, hC.x) - eB.x), 0.0f), 1.0f);
        o.y = fminf(fmaxf(xr.y - (max3f(hA.y, hB.y, hC.y) - eB.y), 0.0f), 1.0f);
        o.z = fminf(fmaxf(xr.z - (max3f(hA.z, hB.z, hC.z) - eB.z), 0.0f), 1.0f);
        o.w = fminf(fmaxf(xr.w - (max3f(hA.w, hB.w, hC.w) - eB.w), 0.0f), 1.0f);

        if (MODE != 2)
            *(float4*)(dst + (size_t)r * IMG_W + colbase) = o;

        if (MODE == 2) {   // tp = sum(skel_pred * tgt)
            unsigned wd = g_tgtbits[(size_t)plane * PLANE_WORDS
                                    + r * WORDS_PER_ROW + (colbase >> 5)];
            int sh = (lane * 4) & 31;
            if ((wd >> (sh + 0)) & 1) acc += o.x;
            if ((wd >> (sh + 1)) & 1) acc += o.y;
            if ((wd >> (sh + 2)) & 1) acc += o.z;
            if ((wd >> (sh + 3)) & 1) acc += o.w;
        }
        if (MODE == 0) {   // ts = sum(skel_gt * probs); probs = xr here
            unsigned wd = g_gbits1[(size_t)plane * PLANE_WORDS
                                   + r * WORDS_PER_ROW + (colbase >> 5)];
            int sh = (lane * 4) & 31;
            if ((wd >> (sh + 0)) & 1) acc += xr.x;
            if ((wd >> (sh + 1)) & 1) acc += xr.y;
            if ((wd >> (sh + 2)) & 1) acc += xr.z;
            if ((wd >> (sh + 3)) & 1) acc += xr.w;
        }
        hA = hB; hB = hC; eB = eC; xr = xb;
    }
#undef LOADROW
#undef STEP

    if (MODE == 0 || MODE == 2) {
        __shared__ float sred[256];
        const int t = threadIdx.x;
        sred[t] = acc;
        __syncthreads();
        for (int o2 = 128; o2 > 0; o2 >>= 1) {
            if (t < o2) sred[t] += sred[t + o2];
            __syncthreads();
        }
        if (t == 0) {
            int idx = plane * 32 + blockIdx.y * 8 + s;
            if (MODE == 0) g_ts_part[idx] = sred[0];
            else           g_tp_part[idx] = sred[0];
        }
    }
}

// ---------------------------------------------------------------------------
__global__ void final_kernel(float* __restrict__ out)
{
    __shared__ float terms[NBATCH];
    const int t = threadIdx.x;
    if (t < NBATCH) {
        float tp = 0.0f, ts = 0.0f;
        for (int c = 0; c < 32; ++c) {
            tp += g_tp_part[t * 32 + c];
            ts += g_ts_part[t * 32 + c];
        }
        float denom = tp + ts;
        float cl = (denom > 0.0f)
                 ? (2.0f * tp * ts + 1e-6f) / (denom + 1e-6f)
                 : 1.0f;
        cl = fminf(fmaxf(cl, 0.0f), 1.0f);
        terms[t] = 1.0f - cl;
    }
    __syncthreads();
    if (t == 0) {
        float s = 0.0f;
        for (int i = 0; i < NBATCH; ++i) s += terms[i];
        out[0] = s / (float)NBATCH;
    }
}

// ---------------------------------------------------------------------------
extern "C" void kernel_launch(void* const* d_in, const int* in_sizes, int n_in,
                              void* d_out, int out_size)
{
    const float* logits = (const float*)d_in[0];
    const int4*  tgt4   = (const int4*)d_in[1];

    pack_bits<<<512, 256>>>(tgt4);

    dim3 bg(4, NBATCH);
    for (int k = 0; k < NITERS; ++k)
        iter_bits_kernel<<<bg, 256>>>(k & 1);   // ends in g_gbits1

    dim3 fg(8, 4, NBATCH);
    iter_fp<0><<<fg, 256>>>(logits, 1);  // logits -> buf0, ts partials
    iter_fp<1><<<fg, 256>>>(logits, 0);  // buf0 -> buf1
    iter_fp<1><<<fg, 256>>>(logits, 1);  // buf1 -> buf0
    iter_fp<1><<<fg, 256>>>(logits, 0);  // buf0 -> buf1
    iter_fp<2><<<fg, 256>>>(logits, 1);  // buf1 -> tp partials (no write)

    final_kernel<<<1, 32>>>((float*)d_out);
}